// round 5
// baseline (speedup 1.0000x reference)
#include <cuda_runtime.h>
#include <math.h>

// ---------------- global scratch (allocation-free rule) ----------------
static __device__ float2 g_p1[4096 * 845];   // L1 pooled output as {silu, t}
static __device__ float2 g_p2[4096 * 405];   // L2 output as {silu, t}

// fp32 cubic-coefficient tables: entry (row, j) = float4(c0,c1,c2,c3), j in [0,10]
static __device__ float4 g_c1[45 * 11];
static __device__ float4 g_c2[625 * 11];
static __device__ float4 g_c3[90 * 11];
// transposed base weights (fp32), padded: wbT[f*8 + o]
static __device__ float g_wbT1[9 * 8];
static __device__ float g_wbT2[125 * 8];
static __device__ float g_wbT3[45 * 8];

__device__ __forceinline__ float silu_f(float x) {
    return __fdividef(x, 1.0f + __expf(-x));
}
// map raw value -> spline coordinate t = j + u (tap base j = floor(t))
__device__ __forceinline__ float tmap(float x) { return (x + 1.0f) * 2.5f + 3.0f; }

__device__ __forceinline__ float cubic4(float4 q, float u) {
    return ((q.w * u + q.z) * u + q.y) * u + q.x;
}

// ---------------- setup: build coefficient + wbT tables ----------------
__device__ __forceinline__ float4 coef_from_w(const float* __restrict__ ws, int row, int j) {
    float w[4];
#pragma unroll
    for (int k = 0; k < 4; k++) {
        int g = j - 3 + k;
        w[k] = (g >= 0 && g <= 7) ? ws[row * 8 + g] : 0.0f;
    }
    const float s6 = 1.0f / 6.0f;
    float4 c;
    c.x = (w[0] + 4.0f * w[1] + w[2]) * s6;
    c.y = (w[2] - w[0]) * 0.5f;
    c.z = (w[0] - 2.0f * w[1] + w[2]) * 0.5f;
    c.w = (-w[0] + 3.0f * w[1] - 3.0f * w[2] + w[3]) * s6;
    return c;
}

__global__ void build_tables(const float* __restrict__ ws1, const float* __restrict__ ws2,
                             const float* __restrict__ ws3, const float* __restrict__ wb1,
                             const float* __restrict__ wb2, const float* __restrict__ wb3) {
    int stride = gridDim.x * blockDim.x;
    int tid = blockIdx.x * blockDim.x + threadIdx.x;
    for (int i = tid; i < 45 * 11; i += stride) g_c1[i] = coef_from_w(ws1, i / 11, i % 11);
    for (int i = tid; i < 625 * 11; i += stride) g_c2[i] = coef_from_w(ws2, i / 11, i % 11);
    for (int i = tid; i < 90 * 11; i += stride) g_c3[i] = coef_from_w(ws3, i / 11, i % 11);
    for (int i = tid; i < 9 * 8; i += stride) {
        int f = i / 8, o = i % 8;
        g_wbT1[i] = (o < 5) ? wb1[o * 9 + f] : 0.0f;
    }
    for (int i = tid; i < 125 * 8; i += stride) {
        int f = i / 8, o = i % 8;
        g_wbT2[i] = (o < 5) ? wb2[o * 125 + f] : 0.0f;
    }
    for (int i = tid; i < 45 * 8; i += stride) {
        int f = i / 8, o = i % 8;
        g_wbT3[i] = (o < 2) ? wb3[o * 45 + f] : 0.0f;
    }
}

// ---------------- Kernel 1: conv3(Cin=1,O=5) + maxpool2, 3 imgs/block ----------------
#define K1_IMGS 3
__global__ void __launch_bounds__(256)
k1_conv_pool(const float* __restrict__ x, int B) {
    __shared__ __align__(16) float wbTs[9 * 8];
    __shared__ float4 c1s[45 * 11];
    __shared__ float2 px[K1_IMGS * 784];
    int tid = threadIdx.x;
    int b0 = blockIdx.x * K1_IMGS;
    int nimg = min(K1_IMGS, B - b0);

    for (int i = tid; i < 45 * 11; i += 256) c1s[i] = g_c1[i];
    if (tid < 72) wbTs[tid] = g_wbT1[tid];
    for (int i = tid; i < nimg * 784; i += 256) {
        float v = x[b0 * 784 + i];
        px[i] = make_float2(silu_f(v), tmap(v));
    }
    __syncthreads();

    for (int task = tid; task < nimg * 169; task += 256) {
        int li = task / 169, p = task % 169;
        int ph = p / 13, pw = p % 13;
        float best[5];
#pragma unroll
        for (int o = 0; o < 5; o++) best[o] = -3.0e38f;

        for (int d = 0; d < 4; d++) {
            int y = 2 * ph + (d >> 1), xx = 2 * pw + (d & 1);
            float a0 = 0, a1 = 0, a2 = 0, a3 = 0, a4 = 0;
#pragma unroll
            for (int r = 0; r < 3; r++)
#pragma unroll
            for (int c = 0; c < 3; c++) {
                int f = r * 3 + c;
                float2 st = px[li * 784 + (y + r) * 28 + xx + c];
                float4 wbv = *reinterpret_cast<const float4*>(&wbTs[f * 8]);
                float wb4 = wbTs[f * 8 + 4];
                a0 += st.x * wbv.x; a1 += st.x * wbv.y; a2 += st.x * wbv.z;
                a3 += st.x * wbv.w; a4 += st.x * wb4;
                float fj = floorf(st.y);
                int j = (int)fj;
                float u = st.y - fj;
                if ((unsigned)j <= 10u) {
                    int i0 = f * 11 + j;
                    a0 += cubic4(c1s[i0], u);
                    a1 += cubic4(c1s[i0 + 99], u);
                    a2 += cubic4(c1s[i0 + 198], u);
                    a3 += cubic4(c1s[i0 + 297], u);
                    a4 += cubic4(c1s[i0 + 396], u);
                }
            }
            best[0] = fmaxf(best[0], a0); best[1] = fmaxf(best[1], a1);
            best[2] = fmaxf(best[2], a2); best[3] = fmaxf(best[3], a3);
            best[4] = fmaxf(best[4], a4);
        }
#pragma unroll
        for (int o = 0; o < 5; o++) {
            float v = best[o];
            g_p1[(b0 + li) * 845 + o * 169 + p] = make_float2(silu_f(v), tmap(v));
        }
    }
}

// ---------------- Kernel 2: conv5(Cin=5,O=5), 12 imgs/block, 1024 thr ----------------
// smem layout (bytes): wbTs [0,4000) (LDS.128 -> 16-aligned base);
// c2s float4 [4000, 114000); in float2 [114000, 195120)
#define K2_IMGS 12
#define K2_SMEM (4000 + 6875 * 16 + K2_IMGS * 845 * 8)
__global__ void __launch_bounds__(1024, 1)
k2_conv(int B) {
    extern __shared__ __align__(16) char smraw[];
    float*  wbTs = reinterpret_cast<float*>(smraw);                   // 1000
    float4* c2s  = reinterpret_cast<float4*>(smraw + 4000);           // 6875
    float2* in   = reinterpret_cast<float2*>(smraw + 4000 + 6875 * 16); // 12*845
    int tid = threadIdx.x;
    int b0 = blockIdx.x * K2_IMGS;
    int nimg = min(K2_IMGS, B - b0);

    for (int i = tid; i < 6875; i += 1024) c2s[i] = g_c2[i];
    for (int i = tid; i < 1000; i += 1024) wbTs[i] = g_wbT2[i];
    for (int i = tid; i < nimg * 845; i += 1024) in[i] = g_p1[b0 * 845 + i];
    __syncthreads();

    int li = tid / 81, pos = tid % 81;
    if (li >= nimg) return;
    int oy = pos / 9, ox = pos % 9;

    float a0 = 0, a1 = 0, a2 = 0, a3 = 0, a4 = 0;
    for (int c = 0; c < 5; c++) {
        const float2* inc = &in[li * 845 + c * 169];
        for (int kh = 0; kh < 5; kh++) {
            const float2* row = &inc[(oy + kh) * 13 + ox];
            int fbase = (c * 5 + kh) * 5;
#pragma unroll
            for (int kw = 0; kw < 5; kw++) {
                int f = fbase + kw;
                float2 st = row[kw];
                float4 wbv = *reinterpret_cast<const float4*>(&wbTs[f * 8]);
                float wb4 = wbTs[f * 8 + 4];
                a0 += st.x * wbv.x; a1 += st.x * wbv.y; a2 += st.x * wbv.z;
                a3 += st.x * wbv.w; a4 += st.x * wb4;
                float fj = floorf(st.y);
                int j = (int)fj;
                float u = st.y - fj;
                if ((unsigned)j <= 10u) {
                    int i0 = f * 11 + j;
                    a0 += cubic4(c2s[i0], u);
                    a1 += cubic4(c2s[i0 + 1375], u);
                    a2 += cubic4(c2s[i0 + 2750], u);
                    a3 += cubic4(c2s[i0 + 4125], u);
                    a4 += cubic4(c2s[i0 + 5500], u);
                }
            }
        }
    }
    int b = b0 + li;
    float acc[5] = {a0, a1, a2, a3, a4};
#pragma unroll
    for (int o = 0; o < 5; o++) {
        float v = acc[o];
        g_p2[b * 405 + o * 81 + pos] = make_float2(silu_f(v), tmap(v));
    }
}

// ---------------- Kernel 3: conv3(Cin=5,O=2) + flatten + FC, 16 imgs/block ----------------
// smem (bytes): c3s fp32 float4 [0,15840); in [15840,67680); fw stride-100 [67680,147680);
// h stride-100 [147680,154080); wbT [154080,155520); fb [155520,156320)
#define K3_IMGS 16
#define K3_SMEM (90 * 11 * 16 + K3_IMGS * 405 * 8 + (200 * 100 + K3_IMGS * 100 + 360 + 200) * 4)
__global__ void __launch_bounds__(512)
k3_conv_fc(const float* __restrict__ fcw, const float* __restrict__ fcb,
           float* __restrict__ out, int B) {
    extern __shared__ __align__(16) char smraw3[];
    float4* c3s = reinterpret_cast<float4*>(smraw3);              // 990
    float2* in  = reinterpret_cast<float2*>(smraw3 + 15840);      // 16*405
    float*  fw  = reinterpret_cast<float*>(smraw3 + 67680);       // 200*100 (pad)
    float*  h   = fw + 200 * 100;                                 // 16*100 (pad)
    float*  wbTs = h + K3_IMGS * 100;                             // 360
    float*  fb  = wbTs + 360;                                     // 200
    int tid = threadIdx.x;
    int b0 = blockIdx.x * K3_IMGS;
    int nimg = min(K3_IMGS, B - b0);

    for (int i = tid; i < 990; i += 512) c3s[i] = g_c3[i];
    for (int i = tid; i < 360; i += 512) wbTs[i] = g_wbT3[i];
    for (int i = tid; i < 200 * 98; i += 512) fw[(i / 98) * 100 + (i % 98)] = fcw[i];
    for (int i = tid; i < 200; i += 512) { fw[i * 100 + 98] = 0.0f; fw[i * 100 + 99] = 0.0f; }
    for (int i = tid; i < K3_IMGS; i += 512) { h[i * 100 + 98] = 0.0f; h[i * 100 + 99] = 0.0f; }
    if (tid < 200) fb[tid] = fcb[tid];
    for (int i = tid; i < nimg * 405; i += 512) in[i] = g_p2[b0 * 405 + i];
    __syncthreads();

    for (int task = tid; task < nimg * 49; task += 512) {
        int li = task / 49, pos = task % 49;
        int oy = pos / 7, ox = pos % 7;
        float a0 = 0, a1 = 0;
        for (int c = 0; c < 5; c++) {
#pragma unroll
            for (int kh = 0; kh < 3; kh++)
#pragma unroll
            for (int kw = 0; kw < 3; kw++) {
                int f = (c * 3 + kh) * 3 + kw;
                float2 st = in[li * 405 + c * 81 + (oy + kh) * 9 + ox + kw];
                a0 += st.x * wbTs[f * 8 + 0];
                a1 += st.x * wbTs[f * 8 + 1];
                float fj = floorf(st.y);
                int j = (int)fj;
                float u = st.y - fj;
                if ((unsigned)j <= 10u) {
                    int i0 = f * 11 + j;
                    a0 += cubic4(c3s[i0], u);
                    a1 += cubic4(c3s[i0 + 495], u);
                }
            }
        }
        h[li * 100 + pos]      = a0;   // flatten order o*49 + pos
        h[li * 100 + 49 + pos] = a1;
    }
    __syncthreads();

    const float4* h4  = reinterpret_cast<const float4*>(h);
    const float4* fw4 = reinterpret_cast<const float4*>(fw);
    for (int task = tid; task < nimg * 200; task += 512) {
        int li = task / 200, o = task % 200;
        float acc = fb[o];
#pragma unroll
        for (int t = 0; t < 25; t++) {
            float4 hv = h4[li * 25 + t];
            float4 wv = fw4[o * 25 + t];
            acc += hv.x * wv.x + hv.y * wv.y + hv.z * wv.z + hv.w * wv.w;
        }
        out[(b0 + li) * 200 + o] = acc;
    }
}

extern "C" void kernel_launch(void* const* d_in, const int* in_sizes, int n_in,
                              void* d_out, int out_size) {
    const float* x   = (const float*)d_in[0];
    const float* wb1 = (const float*)d_in[1];
    const float* ws1 = (const float*)d_in[2];
    const float* wb2 = (const float*)d_in[3];
    const float* ws2 = (const float*)d_in[4];
    const float* wb3 = (const float*)d_in[5];
    const float* ws3 = (const float*)d_in[6];
    const float* fcw = (const float*)d_in[7];
    const float* fcb = (const float*)d_in[8];
    float* out = (float*)d_out;

    int B = in_sizes[0] / 784;

    static int configured = -1;
    if (configured < 0) {
        cudaFuncSetAttribute(k2_conv, cudaFuncAttributeMaxDynamicSharedMemorySize, K2_SMEM);
        cudaFuncSetAttribute(k3_conv_fc, cudaFuncAttributeMaxDynamicSharedMemorySize, K3_SMEM);
        configured = 1;
    }

    build_tables<<<32, 256>>>(ws1, ws2, ws3, wb1, wb2, wb3);
    k1_conv_pool<<<(B + K1_IMGS - 1) / K1_IMGS, 256>>>(x, B);
    k2_conv<<<(B + K2_IMGS - 1) / K2_IMGS, 1024, K2_SMEM>>>(B);
    k3_conv_fc<<<(B + K3_IMGS - 1) / K3_IMGS, 512, K3_SMEM>>>(fcw, fcb, out, B);
}